// round 6
// baseline (speedup 1.0000x reference)
#include <cuda_runtime.h>

// AdaptiveMemory, split into two kernels to break the per-row serial chain
// (h-load -> dot -> shfl-reduce -> coef) off the bulk-bandwidth path.
//
//  K1: alpha/coef per row  (reads h: 16 MB)  -> g_coefs[row] = {cM, cH}
//  K2: out = cM*mem[vid] + cH*h              (pure streaming, 48 MB)
//
// B = 4096, D = 1024.

#define D_DIM    1024
#define CHUNKS   8            // (D/4) / 32 lanes
#define B_MAX    4096

__device__ float2 g_coefs[B_MAX];

// ---------------- K1: warp per row, shfl butterfly reduce ----------------
__global__ __launch_bounds__(128, 8)
void coef_kernel(const float* __restrict__ h_last,
                 const float* __restrict__ W_alpha,
                 const float* __restrict__ b_alpha,
                 const float* __restrict__ medium_decay) {
    const int warp = threadIdx.x >> 5;
    const int lane = threadIdx.x & 31;
    const int row  = blockIdx.x * 4 + warp;

    const float4* h4 = reinterpret_cast<const float4*>(h_last + (size_t)row * D_DIM);
    const float4* w4 = reinterpret_cast<const float4*>(W_alpha);

    float p = 0.0f;
    #pragma unroll
    for (int j = 0; j < CHUNKS; j++) {
        float4 hv = h4[lane + 32 * j];
        float4 wv = w4[lane + 32 * j];
        p += hv.x * wv.x + hv.y * wv.y + hv.z * wv.z + hv.w * wv.w;
    }

    #pragma unroll
    for (int off = 16; off > 0; off >>= 1)
        p += __shfl_xor_sync(0xFFFFFFFFu, p, off);

    if (lane == 0) {
        const float sum   = p + b_alpha[0];
        const float alpha = 1.0f / (1.0f + __expf(-sum));
        const float d     = medium_decay[0];
        float2 c;
        c.x = d + (1.0f - d) * alpha;        // cM
        c.y = (1.0f - d) * (1.0f - alpha);   // cH
        g_coefs[row] = c;
    }
}

// ---------------- K2: pure streaming blend (no reductions) ----------------
// Flat: one float4 per thread. 256 float4 per row -> row = idx >> 8.
// vids/coefs loads are warp-uniform (warps never straddle a row boundary).
__global__ __launch_bounds__(256, 8)
void blend_kernel(const float* __restrict__ h_last,
                  const int* __restrict__ vids,
                  const float* __restrict__ mem,
                  float* __restrict__ out,
                  int n_mem_rows) {
    const int idx = blockIdx.x * blockDim.x + threadIdx.x;   // float4 index
    const int row = idx >> 8;
    const int col = idx & 255;

    int vid = vids[row];
    if (vid < 0) vid = 0;
    if (vid >= n_mem_rows) vid = n_mem_rows - 1;

    const float4 hv = reinterpret_cast<const float4*>(h_last + (size_t)row * D_DIM)[col];
    const float4 mv = reinterpret_cast<const float4*>(mem + (size_t)vid * D_DIM)[col];
    const float2 c  = g_coefs[row];

    float4 o;
    o.x = c.x * mv.x + c.y * hv.x;
    o.y = c.x * mv.y + c.y * hv.y;
    o.z = c.x * mv.z + c.y * hv.z;
    o.w = c.x * mv.w + c.y * hv.w;

    reinterpret_cast<float4*>(out + (size_t)row * D_DIM)[col] = o;
}

extern "C" void kernel_launch(void* const* d_in, const int* in_sizes, int n_in,
                              void* d_out, int out_size) {
    const float* h_last       = (const float*)d_in[0];
    const int*   vids         = (const int*)d_in[1];
    const float* mem          = (const float*)d_in[2];
    const float* W_alpha      = (const float*)d_in[3];
    const float* b_alpha      = (const float*)d_in[4];
    const float* medium_decay = (const float*)d_in[5];
    float*       out          = (float*)d_out;

    const int B          = in_sizes[0] / D_DIM;  // 4096
    const int n_mem_rows = in_sizes[2] / D_DIM;  // 100000

    coef_kernel<<<B / 4, 128>>>(h_last, W_alpha, b_alpha, medium_decay);

    const int total_f4 = B * (D_DIM / 4);        // 1,048,576
    blend_kernel<<<total_f4 / 256, 256>>>(h_last, vids, mem, out, n_mem_rows);
}

// round 7
// speedup vs baseline: 1.2054x; 1.2054x over previous
#include <cuda_runtime.h>
#include <cstdint>

// AdaptiveMemory: out[row] = cM*mem[vids[row]] + cH*h_last[row]
//   alpha = sigmoid(dot(h,W)+b); cM = d+(1-d)*a; cH = (1-d)*(1-a)
// B=4096, D=1024 (row = 4KB).
//
// All bulk loads go through cp.async.bulk (UBLKCP) into SMEM instead of LDG:
// the LDG path is capped by the per-SM L1tex outstanding-line queue (~4 TB/s
// chip-wide); the bulk-copy engine has no such depth cap. 4 rows per CTA,
// 32KB smem staged per CTA, ~224KB in flight per SM.

#define D_DIM     1024
#define ROW_BYTES 4096
#define ROWS_CTA  4
#define THREADS   128
#define CHUNKS    8     // (D/4)/32

__device__ __forceinline__ uint32_t smem_u32(const void* p) {
    uint32_t a;
    asm("{ .reg .u64 t; cvta.to.shared.u64 t, %1; cvt.u32.u64 %0, t; }"
        : "=r"(a) : "l"(p));
    return a;
}

__device__ __forceinline__ void bulk_g2s(uint32_t dst, const void* src,
                                         uint32_t bytes, uint32_t mbar) {
    asm volatile(
        "cp.async.bulk.shared::cluster.global.mbarrier::complete_tx::bytes "
        "[%0], [%1], %2, [%3];"
        :: "r"(dst), "l"(src), "r"(bytes), "r"(mbar) : "memory");
}

__global__ __launch_bounds__(THREADS)
void adaptive_memory_kernel(const float* __restrict__ h_last,
                            const int* __restrict__ vids,
                            const float* __restrict__ mem,
                            const float* __restrict__ W_alpha,
                            const float* __restrict__ b_alpha,
                            const float* __restrict__ medium_decay,
                            float* __restrict__ out,
                            int n_mem_rows) {
    extern __shared__ char smem[];
    // Layout: [0:8) mbarrier | [128 : 128+16K) h tiles | [128+16K : 128+32K) mem tiles
    const uint32_t sbase = smem_u32(smem);
    const uint32_t mbar  = sbase;
    const uint32_t h_sm  = sbase + 128;
    const uint32_t m_sm  = sbase + 128 + ROWS_CTA * ROW_BYTES;

    const int tid  = threadIdx.x;
    const int warp = tid >> 5;
    const int lane = tid & 31;
    const int row0 = blockIdx.x * ROWS_CTA;

    if (tid == 0) {
        asm volatile("mbarrier.init.shared.b64 [%0], 1;" :: "r"(mbar) : "memory");
    }
    __syncthreads();

    if (tid == 0) {
        asm volatile("mbarrier.arrive.expect_tx.shared.b64 _, [%0], %1;"
                     :: "r"(mbar), "r"(2u * ROWS_CTA * ROW_BYTES) : "memory");
        #pragma unroll
        for (int r = 0; r < ROWS_CTA; r++) {
            int vid = vids[row0 + r];
            if (vid < 0) vid = 0;
            if (vid >= n_mem_rows) vid = n_mem_rows - 1;
            bulk_g2s(h_sm + r * ROW_BYTES, h_last + (size_t)(row0 + r) * D_DIM,
                     ROW_BYTES, mbar);
            bulk_g2s(m_sm + r * ROW_BYTES, mem + (size_t)vid * D_DIM,
                     ROW_BYTES, mbar);
        }
    }

    // Wait for all 32KB to land (acquire: generic LDS follows).
    {
        asm volatile(
            "{\n\t"
            ".reg .pred P;\n\t"
            "WAIT_%=:\n\t"
            "mbarrier.try_wait.parity.acquire.cta.shared::cta.b64 P, [%0], 0, 0x989680;\n\t"
            "@P bra DONE_%=;\n\t"
            "bra WAIT_%=;\n\t"
            "DONE_%=:\n\t"
            "}"
            :: "r"(mbar) : "memory");
    }

    // Warp w owns row row0+w. Dot(h, W) from smem (W via LDG, L1/L2-resident).
    const float4* hs = reinterpret_cast<const float4*>(smem + 128 + warp * ROW_BYTES);
    const float4* ms = reinterpret_cast<const float4*>(smem + 128 + ROWS_CTA * ROW_BYTES
                                                        + warp * ROW_BYTES);
    const float4* w4 = reinterpret_cast<const float4*>(W_alpha);

    float p = 0.0f;
    #pragma unroll
    for (int j = 0; j < CHUNKS; j++) {
        float4 hv = hs[lane + 32 * j];
        float4 wv = w4[lane + 32 * j];
        p += hv.x * wv.x + hv.y * wv.y + hv.z * wv.z + hv.w * wv.w;
    }

    #pragma unroll
    for (int off = 16; off > 0; off >>= 1)
        p += __shfl_xor_sync(0xFFFFFFFFu, p, off);

    const float sum   = p + b_alpha[0];
    const float alpha = 1.0f / (1.0f + __expf(-sum));
    const float d     = medium_decay[0];
    const float cM    = d + (1.0f - d) * alpha;
    const float cH    = (1.0f - d) * (1.0f - alpha);

    float4* o4 = reinterpret_cast<float4*>(out + (size_t)(row0 + warp) * D_DIM);
    #pragma unroll
    for (int j = 0; j < CHUNKS; j++) {
        float4 hv = hs[lane + 32 * j];
        float4 mv = ms[lane + 32 * j];
        float4 o;
        o.x = cM * mv.x + cH * hv.x;
        o.y = cM * mv.y + cH * hv.y;
        o.z = cM * mv.z + cH * hv.z;
        o.w = cM * mv.w + cH * hv.w;
        o4[lane + 32 * j] = o;
    }
}

extern "C" void kernel_launch(void* const* d_in, const int* in_sizes, int n_in,
                              void* d_out, int out_size) {
    const float* h_last       = (const float*)d_in[0];
    const int*   vids         = (const int*)d_in[1];
    const float* mem          = (const float*)d_in[2];
    const float* W_alpha      = (const float*)d_in[3];
    const float* b_alpha      = (const float*)d_in[4];
    const float* medium_decay = (const float*)d_in[5];
    float*       out          = (float*)d_out;

    const int B          = in_sizes[0] / D_DIM;  // 4096
    const int n_mem_rows = in_sizes[2] / D_DIM;  // 100000

    const int smem_bytes = 128 + 2 * ROWS_CTA * ROW_BYTES;  // 32,896
    adaptive_memory_kernel<<<B / ROWS_CTA, THREADS, smem_bytes>>>(
        h_last, vids, mem, W_alpha, b_alpha, medium_decay, out, n_mem_rows);
}

// round 8
// speedup vs baseline: 1.4945x; 1.2399x over previous
#include <cuda_runtime.h>

// AdaptiveMemory: out[row] = cM*mem[vids[row]] + cH*h_last[row]
//   alpha = sigmoid(dot(h,W)+b); cM = d+(1-d)*a; cH = (1-d)*(1-a)
// B=4096, D=1024.
// TWO rows per warp, fully interleaved: doubles per-warp MLP, overlaps the
// two shfl reduction chains, and reuses each W chunk for both dots.
// 64-thread CTAs (2 warps = 4 rows) -> grid 1024 (6.92 CTA/SM, balanced).

#define D_DIM   1024
#define CHUNKS  8            // (D/4) / 32 lanes
#define THREADS 64

__global__ __launch_bounds__(THREADS)
void adaptive_memory_kernel(const float* __restrict__ h_last,
                            const int* __restrict__ vids,
                            const float* __restrict__ mem,
                            const float* __restrict__ W_alpha,
                            const float* __restrict__ b_alpha,
                            const float* __restrict__ medium_decay,
                            float* __restrict__ out,
                            int n_mem_rows) {
    const int warp = threadIdx.x >> 5;
    const int lane = threadIdx.x & 31;
    // Warp handles rows rA and rB (adjacent for DRAM page locality).
    const int rA = (blockIdx.x * (THREADS / 32) + warp) * 2;
    const int rB = rA + 1;

    const float4* hA4 = reinterpret_cast<const float4*>(h_last + (size_t)rA * D_DIM);
    const float4* hB4 = reinterpret_cast<const float4*>(h_last + (size_t)rB * D_DIM);
    const float4* w4  = reinterpret_cast<const float4*>(W_alpha);

    int vidA = vids[rA];
    int vidB = vids[rB];
    if (vidA < 0) vidA = 0;
    if (vidA >= n_mem_rows) vidA = n_mem_rows - 1;
    if (vidB < 0) vidB = 0;
    if (vidB >= n_mem_rows) vidB = n_mem_rows - 1;
    const float4* mA4 = reinterpret_cast<const float4*>(mem + (size_t)vidA * D_DIM);
    const float4* mB4 = reinterpret_cast<const float4*>(mem + (size_t)vidB * D_DIM);

    // Front-batch h loads for BOTH rows: 16 outstanding LDG.128/thread.
    float4 hA[CHUNKS], hB[CHUNKS];
    #pragma unroll
    for (int j = 0; j < CHUNKS; j++) hA[j] = hA4[lane + 32 * j];
    #pragma unroll
    for (int j = 0; j < CHUNKS; j++) hB[j] = hB4[lane + 32 * j];

    // Interleaved dots: one W chunk feeds both rows.
    float pA = 0.0f, pB = 0.0f;
    #pragma unroll
    for (int j = 0; j < CHUNKS; j++) {
        float4 wv = w4[lane + 32 * j];
        pA += hA[j].x * wv.x + hA[j].y * wv.y + hA[j].z * wv.z + hA[j].w * wv.w;
        pB += hB[j].x * wv.x + hB[j].y * wv.y + hB[j].z * wv.z + hB[j].w * wv.w;
    }

    // Two independent butterfly reduces, interleaved (latency overlap).
    #pragma unroll
    for (int off = 16; off > 0; off >>= 1) {
        pA += __shfl_xor_sync(0xFFFFFFFFu, pA, off);
        pB += __shfl_xor_sync(0xFFFFFFFFu, pB, off);
    }

    const float bia = b_alpha[0];
    const float d   = medium_decay[0];
    const float aA  = 1.0f / (1.0f + __expf(-(pA + bia)));
    const float aB  = 1.0f / (1.0f + __expf(-(pB + bia)));
    const float cMA = d + (1.0f - d) * aA;
    const float cHA = (1.0f - d) * (1.0f - aA);
    const float cMB = d + (1.0f - d) * aB;
    const float cHB = (1.0f - d) * (1.0f - aB);

    float4* oA4 = reinterpret_cast<float4*>(out + (size_t)rA * D_DIM);
    float4* oB4 = reinterpret_cast<float4*>(out + (size_t)rB * D_DIM);

    // Interleaved epilogues: mem chunks loaded here, consumed immediately.
    #pragma unroll
    for (int j = 0; j < CHUNKS; j++) {
        float4 mA = mA4[lane + 32 * j];
        float4 mB = mB4[lane + 32 * j];
        float4 oA, oB;
        oA.x = cMA * mA.x + cHA * hA[j].x;
        oA.y = cMA * mA.y + cHA * hA[j].y;
        oA.z = cMA * mA.z + cHA * hA[j].z;
        oA.w = cMA * mA.w + cHA * hA[j].w;
        oB.x = cMB * mB.x + cHB * hB[j].x;
        oB.y = cMB * mB.y + cHB * hB[j].y;
        oB.z = cMB * mB.z + cHB * hB[j].z;
        oB.w = cMB * mB.w + cHB * hB[j].w;
        oA4[lane + 32 * j] = oA;
        oB4[lane + 32 * j] = oB;
    }
}

extern "C" void kernel_launch(void* const* d_in, const int* in_sizes, int n_in,
                              void* d_out, int out_size) {
    const float* h_last       = (const float*)d_in[0];
    const int*   vids         = (const int*)d_in[1];
    const float* mem          = (const float*)d_in[2];
    const float* W_alpha      = (const float*)d_in[3];
    const float* b_alpha      = (const float*)d_in[4];
    const float* medium_decay = (const float*)d_in[5];
    float*       out          = (float*)d_out;

    const int B          = in_sizes[0] / D_DIM;  // 4096
    const int n_mem_rows = in_sizes[2] / D_DIM;  // 100000

    const int rows_per_block = (THREADS / 32) * 2;  // 4
    adaptive_memory_kernel<<<B / rows_per_block, THREADS>>>(
        h_last, vids, mem, W_alpha, b_alpha, medium_decay, out, n_mem_rows);
}